// round 13
// baseline (speedup 1.0000x reference)
#include <cuda_runtime.h>
#include <cuda_bf16.h>
#include <cstdint>

// Problem constants
#define B_    32
#define C_    64
#define HW_   1024
#define N_    32768         // B*H*W
#define K_    1024
#define TMZ   128           // points per prep block
#define TMV   64            // points per task
#define NTC   128           // codes per task (slice)
#define NTASK 4096          // 512 point-tiles x 8 slices
#define NBLK  296           // persistent blocks (2 per SM)

// ---------------------------------------------------------------------------
// Scratch (no cudaMalloc allowed)
// ---------------------------------------------------------------------------
__device__ __align__(16) unsigned short g_xb[N_ * C_];  // bf16 z, row-major [n][c]
__device__ __align__(16) float g_xrm[N_ * C_];          // fp32 z, row-major [n][c]
__device__ __align__(16) unsigned short g_c1[K_ * C_];  // bf16 codebook [k][c]
__device__ float g_hn[K_];                    // 0.5*||c_k||^2
__device__ float g_xS[N_];                    // sum_i |x_i| per point
__device__ unsigned long long g_best[N_];     // packed (monotone dist | idx)

// Monotone float<->uint order-preserving mapping
__device__ __forceinline__ unsigned int fkey(float f) {
    unsigned int u = __float_as_uint(f);
    return (u & 0x80000000u) ? ~u : (u | 0x80000000u);
}
__device__ __forceinline__ float fkey_dec(unsigned int k) {
    return (k & 0x80000000u) ? __uint_as_float(k & 0x7fffffffu)
                             : __uint_as_float(~k);
}

__device__ __forceinline__ unsigned int smem_u32(const void* p) {
    unsigned int a;
    asm("{ .reg .u64 t; cvta.to.shared.u64 t, %1; cvt.u32.u64 %0, t; }"
        : "=r"(a) : "l"(p));
    return a;
}

__device__ __forceinline__ void cp_async16(unsigned int dst, const void* src) {
    asm volatile("cp.async.cg.shared.global [%0], [%1], 16;"
                 :: "r"(dst), "l"(src) : "memory");
}

// ---------------------------------------------------------------------------
// Unified prep: 256 blocks x 256 threads.
// All blocks: one 128-point z tile -> bf16 [n][c], fp32 [n][c], sum|x|, g_best.
// Blocks 0-3 additionally: 256 codebook rows each -> bf16 + half norms.
// ---------------------------------------------------------------------------
__global__ __launch_bounds__(256)
void prep_kernel(const float* __restrict__ z, const float* __restrict__ cb) {
    __shared__ float xs[C_ * TMZ];     // [c][m]
    const int tid = threadIdx.x;
    const int n0  = blockIdx.x * TMZ;
    const int b   = n0 / HW_;
    const int hw0 = n0 % HW_;
    const float* zb = z + (size_t)b * C_ * HW_ + hw0;

    {
        int m4 = (tid & 31) * 4;
        int c0 = tid >> 5;
#pragma unroll
        for (int cc = 0; cc < 8; ++cc) {
            int c = c0 + cc * 8;
            *(float4*)&xs[c * TMZ + m4] = *(const float4*)&zb[c * HW_ + m4];
        }
    }
    __syncthreads();

    if (tid < TMZ) {
        const int m = tid;
        const int n = n0 + m;
        const size_t nrow = (size_t)n * C_;
        float S = 0.f;
#pragma unroll
        for (int c0 = 0; c0 < C_; c0 += 8) {
            uint4 p1;
            unsigned short* s1 = (unsigned short*)&p1;
            float xv[8];
#pragma unroll
            for (int j = 0; j < 8; ++j) {
                float x = xs[(c0 + j) * TMZ + m];
                xv[j] = x;
                S += fabsf(x);
                s1[j] = __bfloat16_as_ushort(__float2bfloat16(x));
            }
            *(uint4*)&g_xb[nrow + c0] = p1;
            *(float4*)&g_xrm[nrow + c0]     = make_float4(xv[0], xv[1], xv[2], xv[3]);
            *(float4*)&g_xrm[nrow + c0 + 4] = make_float4(xv[4], xv[5], xv[6], xv[7]);
        }
        g_xS[n]   = S;
        g_best[n] = 0xFFFFFFFFFFFFFFFFull;
    } else {
        // second half of threads initializes the other 128 g_best slots? No —
        // each block owns exactly TMZ points; done above for tid<128.
    }
    if (tid >= TMZ) {
        int n = n0 + (tid - TMZ);      // duplicate-safe: same value written
        (void)n;
    }
    // g_best for tid in [0,128) done; nothing else needed (N_ == 256*128).

    // ---- codebook prep on blocks 0-3 ----
    if (blockIdx.x < 4) {
        const int k = blockIdx.x * 256 + tid;        // 0..1023
        const size_t krow = (size_t)k * C_;
        float s = 0.f;
#pragma unroll
        for (int c0 = 0; c0 < C_; c0 += 8) {
            float4 va = *(const float4*)&cb[krow + c0];
            float4 vb = *(const float4*)&cb[krow + c0 + 4];
            float xv[8] = {va.x, va.y, va.z, va.w, vb.x, vb.y, vb.z, vb.w};
            uint4 p;
            unsigned short* sp = (unsigned short*)&p;
#pragma unroll
            for (int j = 0; j < 8; ++j) {
                float x = xv[j];
                s += x * x;
                sp[j] = __bfloat16_as_ushort(__float2bfloat16(x));
            }
            *(uint4*)&g_c1[krow + c0] = p;
        }
        g_hn[k] = 0.5f * s;
    }
}

// ---------------------------------------------------------------------------
// Persistent vq kernel. 296 blocks x 256 threads, 2 CTAs/SM.
// Per task: cp.async stage (bf16 x 8KB + bf16 codes 16KB, both swizzled, + hn
// + sum|x|) -> HMMA filter -> row-min -> branchless hitmask scan -> smem
// queue -> uniform exact fp32 verify (rows from L2) -> atomicMin(g_best).
// ---------------------------------------------------------------------------
#define XB_OFF   0            // bf16 x [64 m][128B] swizzled : 8192
#define CB_OFF   8192         // bf16 c [128 n][128B] swizzled : 16384
#define HN_OFF   24576        // 512
#define XS_OFF   25088        // 256
#define BUF_SZ   25600
#define SRM_OFF  (2 * BUF_SZ)          // 64 u32 row-min : 256
#define QC_OFF   (2 * BUF_SZ + 256)    // 16
#define OVF_OFF  (2 * BUF_SZ + 272)    // 16
#define QU_OFF   (2 * BUF_SZ + 288)
#define QCAP     1024
#define SMEM_SZ  (QU_OFF + QCAP * 4)   // 55584

__device__ __forceinline__ void stage_task(unsigned int sb, int task, int tid) {
    const int p  = task >> 3;
    const int s  = task & 7;
    const int n0 = p * TMV;
    const char* xsrc = (const char*)(g_xb + (size_t)n0 * C_);
    const char* csrc = (const char*)(g_c1 + (size_t)s * NTC * C_);
    const char* hsrc = (const char*)(g_hn + s * NTC);
    const char* ssrc = (const char*)(g_xS + n0);

    // bf16 x tile: 64 rows x 128B, swizzled 16B chunks (512 chunks)
#pragma unroll
    for (int i = 0; i < 2; ++i) {
        int idx = tid + i * 256;
        int row = idx >> 3;
        int chk = idx & 7;
        cp_async16(sb + XB_OFF + row * 128 + ((chk ^ (row & 7)) * 16),
                   xsrc + idx * 16);
    }
    // bf16 code tile: 128 rows x 128B, swizzled (1024 chunks)
#pragma unroll
    for (int i = 0; i < 4; ++i) {
        int idx = tid + i * 256;
        int row = idx >> 3;
        int chk = idx & 7;
        cp_async16(sb + CB_OFF + row * 128 + ((chk ^ (row & 7)) * 16),
                   csrc + idx * 16);
    }
    if (tid < 32) cp_async16(sb + HN_OFF + tid * 16, hsrc + tid * 16);
    if (tid < 16) cp_async16(sb + XS_OFF + tid * 16, ssrc + tid * 16);
    asm volatile("cp.async.commit_group;" ::: "memory");
}

__global__ __launch_bounds__(256, 2)
void vq_kernel(const float* __restrict__ cb) {
    extern __shared__ char smem[];
    const unsigned int sb0 = smem_u32(smem);
    unsigned int* srm = (unsigned int*)(smem + SRM_OFF);
    int*          qc  = (int*)(smem + QC_OFF);
    unsigned int* ovf = (unsigned int*)(smem + OVF_OFF);
    int*          qu  = (int*)(smem + QU_OFF);

    const int tid  = threadIdx.x;
    const int wid  = tid >> 5;
    const int lane = tid & 31;

    int t   = blockIdx.x;
    int cur = 0;
    if (t < NTASK) stage_task(sb0, t, tid);

    while (t < NTASK) {
        char* buf = smem + cur * BUF_SZ;
        const unsigned int sbuf = sb0 + cur * BUF_SZ;
        const int tnext = t + NBLK;
        if (tnext < NTASK) stage_task(sb0 + (cur ^ 1) * BUF_SZ, tnext, tid);

        if (tnext < NTASK)
            asm volatile("cp.async.wait_group 1;" ::: "memory");
        else
            asm volatile("cp.async.wait_group 0;" ::: "memory");

        if (tid < 64) srm[tid] = 0xFFFFFFFFu;
        if (tid == 0) *qc = 0;
        if (tid < 2)  ovf[tid] = 0u;
        __syncthreads();

        const float* hn = (const float*)(buf + HN_OFF);
        const float* sS = (const float*)(buf + XS_OFF);

        // ---- HMMA filter (64 x 128 x 64) ----
        const int mrow0 = (wid & 3) * 16;
        const int ncol0 = (wid >> 2) * 64;
        const int q  = lane >> 3;
        const int rl = lane & 7;
        const int arow = (q & 1) * 8 + rl;
        const int akh  = q >> 1;
        const int brow = (q >> 1) * 8 + rl;
        const int bkh  = q & 1;

        float acc[8][4];
#pragma unroll
        for (int nt = 0; nt < 8; ++nt)
#pragma unroll
            for (int e = 0; e < 4; ++e) acc[nt][e] = 0.f;

#pragma unroll
        for (int kc = 0; kc < 4; ++kc) {
            unsigned int af[4];
            {
                int row = mrow0 + arow;
                unsigned int addr = sbuf + XB_OFF + row * 128
                                  + (((kc * 2 + akh) ^ (row & 7)) * 16);
                asm volatile("ldmatrix.sync.aligned.m8n8.x4.shared.b16 "
                             "{%0,%1,%2,%3}, [%4];"
                             : "=r"(af[0]), "=r"(af[1]), "=r"(af[2]), "=r"(af[3])
                             : "r"(addr));
            }
            unsigned int bf[4][4];
#pragma unroll
            for (int nt2 = 0; nt2 < 4; ++nt2) {
                int row = ncol0 + nt2 * 16 + brow;
                unsigned int addr = sbuf + CB_OFF + row * 128
                                  + (((kc * 2 + bkh) ^ (row & 7)) * 16);
                asm volatile("ldmatrix.sync.aligned.m8n8.x4.shared.b16 "
                             "{%0,%1,%2,%3}, [%4];"
                             : "=r"(bf[nt2][0]), "=r"(bf[nt2][1]),
                               "=r"(bf[nt2][2]), "=r"(bf[nt2][3])
                             : "r"(addr));
            }
#pragma unroll
            for (int nt = 0; nt < 8; ++nt) {
                int nt2 = nt >> 1, hi = nt & 1;
                asm volatile(
                    "mma.sync.aligned.m16n8k16.row.col.f32.bf16.bf16.f32 "
                    "{%0,%1,%2,%3}, {%4,%5,%6,%7}, {%8,%9}, {%0,%1,%2,%3};"
                    : "+f"(acc[nt][0]), "+f"(acc[nt][1]),
                      "+f"(acc[nt][2]), "+f"(acc[nt][3])
                    : "r"(af[0]), "r"(af[1]), "r"(af[2]), "r"(af[3]),
                      "r"(bf[nt2][hi * 2]), "r"(bf[nt2][hi * 2 + 1]));
            }
        }

        // ---- per-row approx min -> smem (fkey atomicMin) ----
        const int r0 = mrow0 + (lane >> 2);
        const int r1 = r0 + 8;
        {
            float bv0 = 3.4e38f, bv1 = 3.4e38f;
#pragma unroll
            for (int nt = 0; nt < 8; ++nt) {
                int colb = ncol0 + nt * 8 + (lane & 3) * 2;
                float h0 = hn[colb], h1 = hn[colb + 1];
                bv0 = fminf(bv0, fminf(h0 - acc[nt][0], h1 - acc[nt][1]));
                bv1 = fminf(bv1, fminf(h0 - acc[nt][2], h1 - acc[nt][3]));
            }
            bv0 = fminf(bv0, __shfl_xor_sync(0xffffffffu, bv0, 1));
            bv0 = fminf(bv0, __shfl_xor_sync(0xffffffffu, bv0, 2));
            bv1 = fminf(bv1, __shfl_xor_sync(0xffffffffu, bv1, 1));
            bv1 = fminf(bv1, __shfl_xor_sync(0xffffffffu, bv1, 2));
            if ((lane & 3) == 0) {
                atomicMin(&srm[r0], fkey(bv0));
                atomicMin(&srm[r1], fkey(bv1));
            }
        }
        __syncthreads();

        // ---- branchless hitmask scan -> compact queue ----
        {
            const float T0 = fkey_dec(srm[r0]) + sS[r0] * 0.0158f + 0.002f;
            const float T1 = fkey_dec(srm[r1]) + sS[r1] * 0.0158f + 0.002f;
            unsigned int mask = 0;
#pragma unroll
            for (int nt = 0; nt < 8; ++nt) {
                int colb = ncol0 + nt * 8 + (lane & 3) * 2;
                float h0 = hn[colb], h1 = hn[colb + 1];
                mask |= (unsigned int)((h0 - acc[nt][0]) <= T0) << (nt * 4 + 0);
                mask |= (unsigned int)((h1 - acc[nt][1]) <= T0) << (nt * 4 + 1);
                mask |= (unsigned int)((h0 - acc[nt][2]) <= T1) << (nt * 4 + 2);
                mask |= (unsigned int)((h1 - acc[nt][3]) <= T1) << (nt * 4 + 3);
            }
            int cnt = __popc(mask);
            int incl = cnt;
#pragma unroll
            for (int off = 1; off < 32; off <<= 1) {
                int tmp = __shfl_up_sync(0xffffffffu, incl, off);
                if (lane >= off) incl += tmp;
            }
            int total = __shfl_sync(0xffffffffu, incl, 31);
            int base = 0;
            if (lane == 31 && total > 0) base = atomicAdd(qc, total);
            base = __shfl_sync(0xffffffffu, base, 31);
            int pos = base + incl - cnt;
            while (mask) {
                int bgd = __ffs(mask) - 1;
                mask &= mask - 1;
                int nt = bgd >> 2, j = bgd & 3;
                int row = (j < 2) ? r0 : r1;
                int col = ncol0 + nt * 8 + (lane & 3) * 2 + (j & 1);
                if (pos < QCAP) qu[pos] = (row << 8) | col;
                else atomicOr(&ovf[row >> 5], 1u << (row & 31));
                ++pos;
            }
        }
        __syncthreads();

        // ---- uniform exact fp32 verify (x and c rows from L2) ----
        const int p  = t >> 3;
        const int s  = t & 7;
        const int n0 = p * TMV;
        const size_t cbbase = (size_t)s * NTC * C_;
        int qn = *qc;
        if (qn > QCAP) qn = QCAP;
        for (int i = tid; i < qn; i += 256) {
            int e   = qu[i];
            int row = e >> 8;
            int col = e & 255;
            const float4* xr = (const float4*)&g_xrm[(size_t)(n0 + row) * C_];
            const float4* cr = (const float4*)&cb[cbbase + (size_t)col * C_];
            float sv = hn[col];
#pragma unroll
            for (int c4 = 0; c4 < 16; ++c4) {
                float4 xv = xr[c4];
                float4 cv = cr[c4];
                sv = fmaf(-xv.x, cv.x, sv);
                sv = fmaf(-xv.y, cv.y, sv);
                sv = fmaf(-xv.z, cv.z, sv);
                sv = fmaf(-xv.w, cv.w, sv);
            }
            unsigned long long key =
                ((unsigned long long)fkey(sv) << 32)
                | (unsigned int)(s * NTC + col);
            atomicMin(&g_best[n0 + row], key);
        }

        // ---- overflow rows (queue full): exact rescan, ~never taken ----
        if (ovf[0] | ovf[1]) {
            for (int r = 0; r < TMV; ++r) {
                if (!(ovf[r >> 5] & (1u << (r & 31)))) continue;
                if (tid < NTC) {
                    int col = tid;
                    const float4* xr = (const float4*)&g_xrm[(size_t)(n0 + r) * C_];
                    const float4* cr = (const float4*)&cb[cbbase + (size_t)col * C_];
                    float sv = hn[col];
#pragma unroll
                    for (int c4 = 0; c4 < 16; ++c4) {
                        float4 xv = xr[c4];
                        float4 cv = cr[c4];
                        sv = fmaf(-xv.x, cv.x, sv);
                        sv = fmaf(-xv.y, cv.y, sv);
                        sv = fmaf(-xv.z, cv.z, sv);
                        sv = fmaf(-xv.w, cv.w, sv);
                    }
                    unsigned long long key =
                        ((unsigned long long)fkey(sv) << 32)
                        | (unsigned int)(s * NTC + col);
                    atomicMin(&g_best[n0 + r], key);
                }
            }
        }
        __syncthreads();               // buf fully consumed before re-stage

        t = tnext;
        cur ^= 1;
    }
}

// ---------------------------------------------------------------------------
// Finalize: 1024 blocks x 128 threads, 32 points each. float4 output stores.
// ---------------------------------------------------------------------------
#define TF 32
__global__ __launch_bounds__(128)
void finalize_kernel(const float* __restrict__ cb, float* __restrict__ out) {
    __shared__ float scodes[TF * 65];
    __shared__ int   sidx[TF];

    const int tid = threadIdx.x;
    const int n0  = blockIdx.x * TF;
    const int b   = n0 / HW_;
    const int hw0 = n0 % HW_;

    if (tid < TF) {
        unsigned long long key = g_best[n0 + tid];
        int idx = (int)(unsigned int)(key & 0xFFFFFFFFull);
        sidx[tid] = idx;
        out[(size_t)B_ * C_ * HW_ + n0 + tid] = (float)idx;
    }
    __syncthreads();

    {
#pragma unroll
        for (int i = 0; i < 4; ++i) {
            int idx = tid + i * 128;           // 0..511 float4s
            int m   = idx >> 4;
            int c4  = (idx & 15) * 4;
            float4 v = *(const float4*)&cb[sidx[m] * C_ + c4];
            scodes[m * 65 + c4 + 0] = v.x;
            scodes[m * 65 + c4 + 1] = v.y;
            scodes[m * 65 + c4 + 2] = v.z;
            scodes[m * 65 + c4 + 3] = v.w;
        }
    }
    __syncthreads();

    {
        int m4    = (tid & 7) * 4;             // 0..28
        int cbase = tid >> 3;                  // 0..15
        float* ob = out + (size_t)b * C_ * HW_ + hw0;
#pragma unroll
        for (int j = 0; j < 4; ++j) {
            int c = cbase + j * 16;
            float4 w;
            w.x = scodes[(m4 + 0) * 65 + c];
            w.y = scodes[(m4 + 1) * 65 + c];
            w.z = scodes[(m4 + 2) * 65 + c];
            w.w = scodes[(m4 + 3) * 65 + c];
            *(float4*)&ob[c * HW_ + m4] = w;
        }
    }
}

// ---------------------------------------------------------------------------
extern "C" void kernel_launch(void* const* d_in, const int* in_sizes, int n_in,
                              void* d_out, int out_size) {
    const float* z  = (const float*)d_in[0];
    const float* cb = (const float*)d_in[1];
    float* out = (float*)d_out;
    (void)in_sizes; (void)n_in; (void)out_size;

    cudaFuncSetAttribute(vq_kernel,
                         cudaFuncAttributeMaxDynamicSharedMemorySize, SMEM_SZ);

    prep_kernel<<<256, 256>>>(z, cb);
    vq_kernel<<<NBLK, 256, SMEM_SZ>>>(cb);
    finalize_kernel<<<1024, 128>>>(cb, out);
}

// round 14
// speedup vs baseline: 1.2381x; 1.2381x over previous
#include <cuda_runtime.h>
#include <cuda_bf16.h>
#include <cstdint>

// Problem constants
#define B_    32
#define C_    64
#define HW_   1024
#define N_    32768         // B*H*W
#define K_    1024
#define TMV   64            // points per tile
#define NTC   128           // codes per task (slice)
#define NTASK 4096          // 512 tiles x 8 slices, task = tile*8 + slice
#define NBLK  296           // persistent blocks (2 per SM)
#define TPB   14            // tasks per block (contiguous run)

// ---------------------------------------------------------------------------
// Scratch (no cudaMalloc allowed)
// ---------------------------------------------------------------------------
__device__ __align__(16) unsigned short g_c1[K_ * C_];  // bf16 codebook [k][c]
__device__ float g_hn[K_];                    // 0.5*||c_k||^2
__device__ unsigned long long g_best[N_];     // packed (monotone dist | idx)

// Monotone float<->uint order-preserving mapping
__device__ __forceinline__ unsigned int fkey(float f) {
    unsigned int u = __float_as_uint(f);
    return (u & 0x80000000u) ? ~u : (u | 0x80000000u);
}
__device__ __forceinline__ float fkey_dec(unsigned int k) {
    return (k & 0x80000000u) ? __uint_as_float(k & 0x7fffffffu)
                             : __uint_as_float(~k);
}

__device__ __forceinline__ unsigned int smem_u32(const void* p) {
    unsigned int a;
    asm("{ .reg .u64 t; cvta.to.shared.u64 t, %1; cvt.u32.u64 %0, t; }"
        : "=r"(a) : "l"(p));
    return a;
}

__device__ __forceinline__ void cp_async16(unsigned int dst, const void* src) {
    asm volatile("cp.async.cg.shared.global [%0], [%1], 16;"
                 :: "r"(dst), "l"(src) : "memory");
}
#define CP_COMMIT() asm volatile("cp.async.commit_group;" ::: "memory")

// ---------------------------------------------------------------------------
// Prep: bf16 codebook + half norms + g_best init. 128 blocks x 256 threads.
// (verbatim from the 92.9us kernel)
// ---------------------------------------------------------------------------
__global__ __launch_bounds__(256)
void prep_cb_kernel(const float* __restrict__ cb) {
    const int gid = blockIdx.x * 256 + threadIdx.x;   // 0..32767
    if (gid < K_) {
        const int k = gid;
        const size_t krow = (size_t)k * C_;
        float s = 0.f;
#pragma unroll
        for (int c0 = 0; c0 < C_; c0 += 8) {
            float4 va = *(const float4*)&cb[krow + c0];
            float4 vb = *(const float4*)&cb[krow + c0 + 4];
            float xv[8] = {va.x, va.y, va.z, va.w, vb.x, vb.y, vb.z, vb.w};
            uint4 p;
            unsigned short* sp = (unsigned short*)&p;
#pragma unroll
            for (int j = 0; j < 8; ++j) {
                float x = xv[j];
                s += x * x;
                sp[j] = __bfloat16_as_ushort(__float2bfloat16(x));
            }
            *(uint4*)&g_c1[krow + c0] = p;
        }
        g_hn[k] = 0.5f * s;
    }
    g_best[gid] = 0xFFFFFFFFFFFFFFFFull;
}

// ---------------------------------------------------------------------------
// Persistent vq kernel. 296 blocks x 256 threads, 2 CTAs/SM.
// Block bid owns tasks [14*bid, 14*bid+14): consecutive slices of the same
// tile, so the x tile (fp32 stage + bf16 convert + sum|x|) is built once per
// tile run and held; only the code tile double-buffers.
// ---------------------------------------------------------------------------
#define XF_OFF   0                     // fp32 x [64 c][64 m] : 16384
#define XB_OFF   16384                 // bf16 x [64 m][128B] swizzled : 8192
#define CB0_OFF  24576                 // 2 bufs x (cb 16384 + hn 512)
#define CBUF_SZ  16896
#define SS_OFF   (CB0_OFF + 2 * CBUF_SZ)   // 58368 : 256
#define SRM_OFF  (SS_OFF + 256)            // 58624 : 256
#define QC_OFF   (SRM_OFF + 256)           // 58880 : 16
#define OVF_OFF  (QC_OFF + 16)             // 58896 : 16
#define QU_OFF   (OVF_OFF + 16)            // 58912
#define QCAP     1024
#define SMEM_SZ  (QU_OFF + QCAP * 4)       // 63008

__device__ __forceinline__ void stage_x(unsigned int sb, const float* __restrict__ z,
                                        int tile, int tid) {
    const int n0  = tile * TMV;
    const int b   = n0 >> 10;
    const int hw0 = n0 & 1023;
    const char* zsrc = (const char*)(z + (size_t)b * C_ * HW_ + hw0);
#pragma unroll
    for (int i = 0; i < 4; ++i) {
        int idx = tid + i * 256;           // 0..1023 16B chunks
        int c   = idx >> 4;
        int o   = (idx & 15) * 16;
        cp_async16(sb + XF_OFF + idx * 16, zsrc + (size_t)c * HW_ * 4 + o);
    }
}

__device__ __forceinline__ void stage_c(unsigned int cbbase, int task, int tid) {
    const int s = task & 7;
    const char* csrc = (const char*)(g_c1 + (size_t)s * NTC * C_);
    const char* hsrc = (const char*)(g_hn + s * NTC);
#pragma unroll
    for (int i = 0; i < 4; ++i) {
        int idx = tid + i * 256;           // 0..1023 chunks
        int row = idx >> 3;
        int chk = idx & 7;
        cp_async16(cbbase + row * 128 + ((chk ^ (row & 7)) * 16),
                   csrc + idx * 16);
    }
    if (tid < 32) cp_async16(cbbase + 16384 + tid * 16, hsrc + tid * 16);
}

__global__ __launch_bounds__(256, 2)
void vq_kernel(const float* __restrict__ z, const float* __restrict__ cb) {
    extern __shared__ char smem[];
    const unsigned int sb0 = smem_u32(smem);
    float*        xf  = (float*)(smem + XF_OFF);
    float*        sS  = (float*)(smem + SS_OFF);
    unsigned int* srm = (unsigned int*)(smem + SRM_OFF);
    int*          qc  = (int*)(smem + QC_OFF);
    unsigned int* ovf = (unsigned int*)(smem + OVF_OFF);
    int*          qu  = (int*)(smem + QU_OFF);

    const int tid  = threadIdx.x;
    const int wid  = tid >> 5;
    const int lane = tid & 31;

    const int start = blockIdx.x * TPB;
    const int end   = (start + TPB < NTASK) ? start + TPB : NTASK;
    if (start >= NTASK) return;

    int t   = start;
    int cur = 0;
    bool needA = true;
    stage_x(sb0, z, t >> 3, tid);
    stage_c(sb0 + CB0_OFF, t, tid);
    CP_COMMIT();

    while (t < end) {
        const int  tn   = t + 1;
        const bool same = (tn < end) && ((tn >> 3) == (t >> 3));
        if (same) {
            stage_c(sb0 + CB0_OFF + (cur ^ 1) * CBUF_SZ, tn, tid);
            CP_COMMIT();
        }
        if (same)
            asm volatile("cp.async.wait_group 1;" ::: "memory");
        else
            asm volatile("cp.async.wait_group 0;" ::: "memory");

        // ---- Phase A (once per tile): fp32 [c][m] -> bf16 [m][c] + sum|x| ----
        if (needA) {
            __syncthreads();               // make staged xf visible to all
            const int m  = tid >> 2;
            const int c0 = (tid & 3) * 16;
            float v[16];
            float S = 0.f;
#pragma unroll
            for (int j = 0; j < 16; ++j) {
                v[j] = xf[(c0 + j) * 64 + m];
                S += fabsf(v[j]);
            }
            unsigned int pk[8];
#pragma unroll
            for (int j = 0; j < 8; ++j)
                asm("cvt.rn.bf16x2.f32 %0, %1, %2;"
                    : "=r"(pk[j]) : "f"(v[j * 2 + 1]), "f"(v[j * 2]));
            const int cb0i = 2 * (tid & 3);
#pragma unroll
            for (int g = 0; g < 2; ++g) {
                unsigned int addr = sb0 + XB_OFF + m * 128
                                  + (((cb0i + g) ^ (m & 7)) * 16);
                asm volatile("st.shared.v4.b32 [%0], {%1,%2,%3,%4};"
                             :: "r"(addr), "r"(pk[g*4+0]), "r"(pk[g*4+1]),
                                "r"(pk[g*4+2]), "r"(pk[g*4+3]) : "memory");
            }
            S += __shfl_xor_sync(0xffffffffu, S, 1, 4);
            S += __shfl_xor_sync(0xffffffffu, S, 2, 4);
            if ((tid & 3) == 0) sS[m] = S;
            needA = false;
        }
        if (tid < 64) srm[tid] = 0xFFFFFFFFu;
        if (tid == 0) *qc = 0;
        if (tid < 2)  ovf[tid] = 0u;
        __syncthreads();

        const unsigned int cbbase = sb0 + CB0_OFF + cur * CBUF_SZ;
        const float* hn = (const float*)(smem + CB0_OFF + cur * CBUF_SZ + 16384);

        // ---- HMMA filter (64 x 128 x 64) ----
        const int mrow0 = (wid & 3) * 16;
        const int ncol0 = (wid >> 2) * 64;
        const int q  = lane >> 3;
        const int rl = lane & 7;
        const int arow = (q & 1) * 8 + rl;
        const int akh  = q >> 1;
        const int brow = (q >> 1) * 8 + rl;
        const int bkh  = q & 1;

        float acc[8][4];
#pragma unroll
        for (int nt = 0; nt < 8; ++nt)
#pragma unroll
            for (int e = 0; e < 4; ++e) acc[nt][e] = 0.f;

#pragma unroll
        for (int kc = 0; kc < 4; ++kc) {
            unsigned int af[4];
            {
                int row = mrow0 + arow;
                unsigned int addr = sb0 + XB_OFF + row * 128
                                  + (((kc * 2 + akh) ^ (row & 7)) * 16);
                asm volatile("ldmatrix.sync.aligned.m8n8.x4.shared.b16 "
                             "{%0,%1,%2,%3}, [%4];"
                             : "=r"(af[0]), "=r"(af[1]), "=r"(af[2]), "=r"(af[3])
                             : "r"(addr));
            }
            unsigned int bf[4][4];
#pragma unroll
            for (int nt2 = 0; nt2 < 4; ++nt2) {
                int row = ncol0 + nt2 * 16 + brow;
                unsigned int addr = cbbase + row * 128
                                  + (((kc * 2 + bkh) ^ (row & 7)) * 16);
                asm volatile("ldmatrix.sync.aligned.m8n8.x4.shared.b16 "
                             "{%0,%1,%2,%3}, [%4];"
                             : "=r"(bf[nt2][0]), "=r"(bf[nt2][1]),
                               "=r"(bf[nt2][2]), "=r"(bf[nt2][3])
                             : "r"(addr));
            }
#pragma unroll
            for (int nt = 0; nt < 8; ++nt) {
                int nt2 = nt >> 1, hi = nt & 1;
                asm volatile(
                    "mma.sync.aligned.m16n8k16.row.col.f32.bf16.bf16.f32 "
                    "{%0,%1,%2,%3}, {%4,%5,%6,%7}, {%8,%9}, {%0,%1,%2,%3};"
                    : "+f"(acc[nt][0]), "+f"(acc[nt][1]),
                      "+f"(acc[nt][2]), "+f"(acc[nt][3])
                    : "r"(af[0]), "r"(af[1]), "r"(af[2]), "r"(af[3]),
                      "r"(bf[nt2][hi * 2]), "r"(bf[nt2][hi * 2 + 1]));
            }
        }

        // ---- per-row approx min -> smem (fkey atomicMin) ----
        const int r0 = mrow0 + (lane >> 2);
        const int r1 = r0 + 8;
        {
            float bv0 = 3.4e38f, bv1 = 3.4e38f;
#pragma unroll
            for (int nt = 0; nt < 8; ++nt) {
                int colb = ncol0 + nt * 8 + (lane & 3) * 2;
                float h0 = hn[colb], h1 = hn[colb + 1];
                bv0 = fminf(bv0, fminf(h0 - acc[nt][0], h1 - acc[nt][1]));
                bv1 = fminf(bv1, fminf(h0 - acc[nt][2], h1 - acc[nt][3]));
            }
            bv0 = fminf(bv0, __shfl_xor_sync(0xffffffffu, bv0, 1));
            bv0 = fminf(bv0, __shfl_xor_sync(0xffffffffu, bv0, 2));
            bv1 = fminf(bv1, __shfl_xor_sync(0xffffffffu, bv1, 1));
            bv1 = fminf(bv1, __shfl_xor_sync(0xffffffffu, bv1, 2));
            if ((lane & 3) == 0) {
                atomicMin(&srm[r0], fkey(bv0));
                atomicMin(&srm[r1], fkey(bv1));
            }
        }
        __syncthreads();

        // ---- branchless hitmask scan -> compact queue ----
        {
            const float T0 = fkey_dec(srm[r0]) + sS[r0] * 0.0158f + 0.002f;
            const float T1 = fkey_dec(srm[r1]) + sS[r1] * 0.0158f + 0.002f;
            unsigned int mask = 0;
#pragma unroll
            for (int nt = 0; nt < 8; ++nt) {
                int colb = ncol0 + nt * 8 + (lane & 3) * 2;
                float h0 = hn[colb], h1 = hn[colb + 1];
                mask |= (unsigned int)((h0 - acc[nt][0]) <= T0) << (nt * 4 + 0);
                mask |= (unsigned int)((h1 - acc[nt][1]) <= T0) << (nt * 4 + 1);
                mask |= (unsigned int)((h0 - acc[nt][2]) <= T1) << (nt * 4 + 2);
                mask |= (unsigned int)((h1 - acc[nt][3]) <= T1) << (nt * 4 + 3);
            }
            int cnt = __popc(mask);
            int incl = cnt;
#pragma unroll
            for (int off = 1; off < 32; off <<= 1) {
                int tmp = __shfl_up_sync(0xffffffffu, incl, off);
                if (lane >= off) incl += tmp;
            }
            int total = __shfl_sync(0xffffffffu, incl, 31);
            int base = 0;
            if (lane == 31 && total > 0) base = atomicAdd(qc, total);
            base = __shfl_sync(0xffffffffu, base, 31);
            int pos = base + incl - cnt;
            while (mask) {
                int bgd = __ffs(mask) - 1;
                mask &= mask - 1;
                int nt = bgd >> 2, j = bgd & 3;
                int row = (j < 2) ? r0 : r1;
                int col = ncol0 + nt * 8 + (lane & 3) * 2 + (j & 1);
                if (pos < QCAP) qu[pos] = (row << 8) | col;
                else atomicOr(&ovf[row >> 5], 1u << (row & 31));
                ++pos;
            }
        }
        __syncthreads();

        // ---- uniform exact fp32 verify: x from smem, c rows from L2 ----
        const int p  = t >> 3;
        const int s  = t & 7;
        const int n0 = p * TMV;
        const size_t cbgbase = (size_t)s * NTC * C_;
        int qn = *qc;
        if (qn > QCAP) qn = QCAP;
        for (int i = tid; i < qn; i += 256) {
            int e   = qu[i];
            int row = e >> 8;
            int col = e & 255;
            const float4* cr = (const float4*)&cb[cbgbase + (size_t)col * C_];
            float sv = hn[col];
#pragma unroll
            for (int c4 = 0; c4 < 16; ++c4) {
                float4 cv = cr[c4];
                sv = fmaf(-xf[(c4 * 4 + 0) * 64 + row], cv.x, sv);
                sv = fmaf(-xf[(c4 * 4 + 1) * 64 + row], cv.y, sv);
                sv = fmaf(-xf[(c4 * 4 + 2) * 64 + row], cv.z, sv);
                sv = fmaf(-xf[(c4 * 4 + 3) * 64 + row], cv.w, sv);
            }
            unsigned long long key =
                ((unsigned long long)fkey(sv) << 32)
                | (unsigned int)(s * NTC + col);
            atomicMin(&g_best[n0 + row], key);
        }

        // ---- overflow rows (queue full): exact rescan, ~never taken ----
        if (ovf[0] | ovf[1]) {
            for (int r = 0; r < TMV; ++r) {
                if (!(ovf[r >> 5] & (1u << (r & 31)))) continue;
                if (tid < NTC) {
                    int col = tid;
                    const float4* cr = (const float4*)&cb[cbgbase + (size_t)col * C_];
                    float sv = hn[col];
#pragma unroll
                    for (int c4 = 0; c4 < 16; ++c4) {
                        float4 cv = cr[c4];
                        sv = fmaf(-xf[(c4 * 4 + 0) * 64 + r], cv.x, sv);
                        sv = fmaf(-xf[(c4 * 4 + 1) * 64 + r], cv.y, sv);
                        sv = fmaf(-xf[(c4 * 4 + 2) * 64 + r], cv.z, sv);
                        sv = fmaf(-xf[(c4 * 4 + 3) * 64 + r], cv.w, sv);
                    }
                    unsigned long long key =
                        ((unsigned long long)fkey(sv) << 32)
                        | (unsigned int)(s * NTC + col);
                    atomicMin(&g_best[n0 + r], key);
                }
            }
        }
        __syncthreads();               // task fully consumed

        // ---- tile boundary: stage next tile's x + c (Phase A next iter) ----
        if (tn < end && !same) {
            stage_x(sb0, z, tn >> 3, tid);
            stage_c(sb0 + CB0_OFF + (cur ^ 1) * CBUF_SZ, tn, tid);
            CP_COMMIT();
            needA = true;
        }

        t = tn;
        cur ^= 1;
    }
}

// ---------------------------------------------------------------------------
// Finalize: 1024 blocks x 128 threads, 32 points each. float4 output stores.
// ---------------------------------------------------------------------------
#define TF 32
__global__ __launch_bounds__(128)
void finalize_kernel(const float* __restrict__ cb, float* __restrict__ out) {
    __shared__ float scodes[TF * 65];
    __shared__ int   sidx[TF];

    const int tid = threadIdx.x;
    const int n0  = blockIdx.x * TF;
    const int b   = n0 / HW_;
    const int hw0 = n0 % HW_;

    if (tid < TF) {
        unsigned long long key = g_best[n0 + tid];
        int idx = (int)(unsigned int)(key & 0xFFFFFFFFull);
        sidx[tid] = idx;
        out[(size_t)B_ * C_ * HW_ + n0 + tid] = (float)idx;
    }
    __syncthreads();

    {
#pragma unroll
        for (int i = 0; i < 4; ++i) {
            int idx = tid + i * 128;           // 0..511 float4s
            int m   = idx >> 4;
            int c4  = (idx & 15) * 4;
            float4 v = *(const float4*)&cb[sidx[m] * C_ + c4];
            scodes[m * 65 + c4 + 0] = v.x;
            scodes[m * 65 + c4 + 1] = v.y;
            scodes[m * 65 + c4 + 2] = v.z;
            scodes[m * 65 + c4 + 3] = v.w;
        }
    }
    __syncthreads();

    {
        int m4    = (tid & 7) * 4;             // 0..28
        int cbase = tid >> 3;                  // 0..15
        float* ob = out + (size_t)b * C_ * HW_ + hw0;
#pragma unroll
        for (int j = 0; j < 4; ++j) {
            int c = cbase + j * 16;
            float4 w;
            w.x = scodes[(m4 + 0) * 65 + c];
            w.y = scodes[(m4 + 1) * 65 + c];
            w.z = scodes[(m4 + 2) * 65 + c];
            w.w = scodes[(m4 + 3) * 65 + c];
            *(float4*)&ob[c * HW_ + m4] = w;
        }
    }
}

// ---------------------------------------------------------------------------
extern "C" void kernel_launch(void* const* d_in, const int* in_sizes, int n_in,
                              void* d_out, int out_size) {
    const float* z  = (const float*)d_in[0];
    const float* cb = (const float*)d_in[1];
    float* out = (float*)d_out;
    (void)in_sizes; (void)n_in; (void)out_size;

    cudaFuncSetAttribute(vq_kernel,
                         cudaFuncAttributeMaxDynamicSharedMemorySize, SMEM_SZ);

    prep_cb_kernel<<<128, 256>>>(cb);
    vq_kernel<<<NBLK, 256, SMEM_SZ>>>(z, cb);
    finalize_kernel<<<1024, 128>>>(cb, out);
}